// round 16
// baseline (speedup 1.0000x reference)
#include <cuda_runtime.h>
#include <cuda_fp16.h>

#define NNODES 50000
#define NEDGES 800000
#define TOTEDGES (NEDGES + NNODES)

// ---------------- scratch (no allocations allowed) ----------------
__device__ __align__(16) __half g_h[NNODES * 128];   // fp16 gather source
__device__ float g_bufA[NNODES * 128];
__device__ float g_bufB[NNODES * 128];
__device__ float g_es[NNODES * 4];
__device__ float g_ed[NNODES * 4];
__device__ float g_stats[256];
__device__ int   g_deg[NNODES];
__device__ int   g_rowptr[NNODES + 1];
__device__ int   g_cursor[NNODES];
__device__ int   g_csr[TOTEDGES];

// ---------------- f32x2 helpers ----------------
__device__ __forceinline__ void fma2(unsigned long long& d, unsigned long long a,
                                     unsigned long long b) {
    asm("fma.rn.f32x2 %0, %1, %2, %0;" : "+l"(d) : "l"(a), "l"(b));
}
__device__ __forceinline__ unsigned long long bcast2(float x) {
    unsigned long long r;
    asm("mov.b64 %0, {%1, %1};" : "=l"(r) : "f"(x));
    return r;
}
__device__ __forceinline__ float2 unpack2(unsigned long long p) {
    float2 f;
    asm("mov.b64 {%0, %1}, %2;" : "=f"(f.x), "=f"(f.y) : "l"(p));
    return f;
}
__device__ __forceinline__ unsigned h2u(__half2 h) {
    return *reinterpret_cast<unsigned*>(&h);
}
__device__ __forceinline__ float red8(float v) {
    v += __shfl_xor_sync(0xffffffffu, v, 1);
    v += __shfl_xor_sync(0xffffffffu, v, 2);
    v += __shfl_xor_sync(0xffffffffu, v, 4);
    return v;
}
__device__ __forceinline__ float red16(float v) {
    v += __shfl_xor_sync(0xffffffffu, v, 1);
    v += __shfl_xor_sync(0xffffffffu, v, 2);
    v += __shfl_xor_sync(0xffffffffu, v, 4);
    v += __shfl_xor_sync(0xffffffffu, v, 8);
    return v;
}

// ---------------- CSR build ----------------
__global__ void deg_init_kernel(int* deg) {
    int i = blockIdx.x * blockDim.x + threadIdx.x;
    if (i < NNODES) deg[i] = 1;  // self loop
}

__global__ void scan_kernel(const int* __restrict__ deg, int* __restrict__ rowptr,
                            int* __restrict__ cursor) {
    __shared__ int part[1024];
    const int CH = (NNODES + 1023) / 1024;
    int t = threadIdx.x;
    int base = t * CH;
    int s = 0;
    for (int i = 0; i < CH; i++) {
        int idx = base + i;
        if (idx < NNODES) s += deg[idx];
    }
    part[t] = s;
    __syncthreads();
    for (int off = 1; off < 1024; off <<= 1) {
        int v = (t >= off) ? part[t - off] : 0;
        __syncthreads();
        part[t] += v;
        __syncthreads();
    }
    int run = (t == 0) ? 0 : part[t - 1];
    for (int i = 0; i < CH; i++) {
        int idx = base + i;
        if (idx < NNODES) {
            rowptr[idx] = run;
            cursor[idx] = run;
            run += deg[idx];
        }
    }
    if (t == 1023) rowptr[NNODES] = part[1023];
}

// merged scatter: i < NNODES -> self loop; else edge (i - NNODES)
__global__ void scatter_kernel(const int* __restrict__ src, const int* __restrict__ dst,
                               int* __restrict__ cursor, int* __restrict__ csr) {
    int i = blockIdx.x * blockDim.x + threadIdx.x;
    if (i < NNODES) {
        int pos = atomicAdd(&cursor[i], 1);
        csr[pos] = i;
    } else {
        int e = i - NNODES;
        if (e < NEDGES) {
            int d = dst[e];
            int pos = atomicAdd(&cursor[d], 1);
            csr[pos] = src[e];
        }
    }
}

// ---------------- SGEMM (f32x2) + fused BN-affine input + fused es/ed epilogue ----------------
// C output stored fp16 (gather source); es/ed computed from fp32 accumulators.
// CSRCOUNT: trailing blocks (blockIdx.x >= ceil(M/BM)) do the edge-degree histogram instead.
template <int BN, int H, bool AFFINE, bool INRELU, bool CSRCOUNT>
__launch_bounds__(256, 2)
__global__ void gemm_kernel(const float* __restrict__ A, const float* __restrict__ B,
                            __half* __restrict__ C, int M, int K, int N,
                            const float* __restrict__ stats, const float* __restrict__ g,
                            const float* __restrict__ be,
                            const float* __restrict__ a_src, const float* __restrict__ a_dst,
                            float* __restrict__ es, float* __restrict__ ed,
                            const int* __restrict__ e_dst, int* __restrict__ deg) {
    constexpr int BM = 128;
    constexpr int BK = 32;
    constexpr int TN = BN / 16;
    constexpr int LDA = BM + 4;

    __shared__ alignas(16) float AsT[BK * LDA];
    __shared__ alignas(16) float Bs[BK * BN];
    __shared__ float s_sc[128];
    __shared__ float s_sh[128];
    __shared__ float s_as[BN];
    __shared__ float s_ad[BN];

    const int tx = threadIdx.x, ty = threadIdx.y;
    const int t = ty * 16 + tx;

    if (CSRCOUNT) {
        int nblk = (M + BM - 1) / BM;
        if ((int)blockIdx.x >= nblk) {
            int i = ((int)blockIdx.x - nblk) * 256 + t;
            if (i < NEDGES) atomicAdd(&deg[e_dst[i]], 1);
            return;
        }
    }

    const int rowBase = blockIdx.x * BM;

    if (t < BN) {
        s_as[t] = a_src[t];
        s_ad[t] = a_dst[t];
    }

    if (AFFINE) {
        const float invn = 1.f / (float)NNODES;
        for (int c = t; c < K; c += 256) {
            float mean = stats[c] * invn;
            float var = stats[K + c] * invn - mean * mean;
            float scv = g[c] * rsqrtf(var + 1e-5f);
            s_sc[c] = scv;
            s_sh[c] = be[c] - mean * scv;
        }
    }
    __syncthreads();

    unsigned long long acc[4][TN];
#pragma unroll
    for (int p = 0; p < 4; p++)
#pragma unroll
        for (int j = 0; j < TN; j++) acc[p][j] = 0ull;

    for (int k0 = 0; k0 < K; k0 += BK) {
#pragma unroll
        for (int i = t; i < BM * BK / 4; i += 256) {
            int r = i / (BK / 4);
            int kc = (i % (BK / 4)) * 4;
            int rg = rowBase + r;
            float4 v = make_float4(0.f, 0.f, 0.f, 0.f);
            if (rg < M) v = *reinterpret_cast<const float4*>(A + (size_t)rg * K + k0 + kc);
            if (AFFINE) {
                int c = k0 + kc;
                v.x = v.x * s_sc[c] + s_sh[c];
                v.y = v.y * s_sc[c + 1] + s_sh[c + 1];
                v.z = v.z * s_sc[c + 2] + s_sh[c + 2];
                v.w = v.w * s_sc[c + 3] + s_sh[c + 3];
                if (INRELU) {
                    v.x = fmaxf(v.x, 0.f); v.y = fmaxf(v.y, 0.f);
                    v.z = fmaxf(v.z, 0.f); v.w = fmaxf(v.w, 0.f);
                }
            }
            AsT[(kc + 0) * LDA + r] = v.x;
            AsT[(kc + 1) * LDA + r] = v.y;
            AsT[(kc + 2) * LDA + r] = v.z;
            AsT[(kc + 3) * LDA + r] = v.w;
        }
#pragma unroll
        for (int i = t; i < BK * BN / 4; i += 256) {
            int kk = i / (BN / 4);
            int c = (i % (BN / 4)) * 4;
            *reinterpret_cast<float4*>(&Bs[kk * BN + c]) =
                *reinterpret_cast<const float4*>(B + (size_t)(k0 + kk) * N + c);
        }
        __syncthreads();

#pragma unroll
        for (int kk = 0; kk < BK; kk++) {
            const float* arow = &AsT[kk * LDA];
            ulonglong2 aLo = *reinterpret_cast<const ulonglong2*>(arow + ty * 4);
            ulonglong2 aHi = *reinterpret_cast<const ulonglong2*>(arow + 64 + ty * 4);
            unsigned long long bb[TN];
            if (TN == 8) {
                float4 b0 = *reinterpret_cast<const float4*>(&Bs[kk * BN + tx * 4]);
                float4 b1 = *reinterpret_cast<const float4*>(&Bs[kk * BN + 64 + tx * 4]);
                bb[0] = bcast2(b0.x); bb[1] = bcast2(b0.y);
                bb[2] = bcast2(b0.z); bb[3] = bcast2(b0.w);
                bb[4] = bcast2(b1.x); bb[5] = bcast2(b1.y);
                bb[6] = bcast2(b1.z); bb[7] = bcast2(b1.w);
            } else {
                float2 b0 = *reinterpret_cast<const float2*>(&Bs[kk * BN + tx * 2]);
                bb[0] = bcast2(b0.x); bb[1] = bcast2(b0.y);
            }
#pragma unroll
            for (int j = 0; j < TN; j++) {
                fma2(acc[0][j], aLo.x, bb[j]);
                fma2(acc[1][j], aLo.y, bb[j]);
                fma2(acc[2][j], aHi.x, bb[j]);
                fma2(acc[3][j], aHi.y, bb[j]);
            }
        }
        __syncthreads();
    }

#pragma unroll
    for (int p = 0; p < 4; p++) {
        int r0 = rowBase + ((p < 2) ? (ty * 4 + 2 * p) : (64 + ty * 4 + 2 * (p - 2)));
        float2 u[TN];
#pragma unroll
        for (int j = 0; j < TN; j++) u[j] = unpack2(acc[p][j]);

        // C stores (fp16)
        if (TN == 8) {
            if (r0 < M) {
                uint2 lo, hi;
                lo.x = h2u(__floats2half2_rn(u[0].x, u[1].x));
                lo.y = h2u(__floats2half2_rn(u[2].x, u[3].x));
                hi.x = h2u(__floats2half2_rn(u[4].x, u[5].x));
                hi.y = h2u(__floats2half2_rn(u[6].x, u[7].x));
                *reinterpret_cast<uint2*>(C + (size_t)r0 * N + tx * 4) = lo;
                *reinterpret_cast<uint2*>(C + (size_t)r0 * N + 64 + tx * 4) = hi;
            }
            if (r0 + 1 < M) {
                uint2 lo, hi;
                lo.x = h2u(__floats2half2_rn(u[0].y, u[1].y));
                lo.y = h2u(__floats2half2_rn(u[2].y, u[3].y));
                hi.x = h2u(__floats2half2_rn(u[4].y, u[5].y));
                hi.y = h2u(__floats2half2_rn(u[6].y, u[7].y));
                *reinterpret_cast<uint2*>(C + (size_t)(r0 + 1) * N + tx * 4) = lo;
                *reinterpret_cast<uint2*>(C + (size_t)(r0 + 1) * N + 64 + tx * 4) = hi;
            }
        } else {
            if (r0 < M)
                *reinterpret_cast<__half2*>(C + (size_t)r0 * N + tx * 2) =
                    __floats2half2_rn(u[0].x, u[1].x);
            if (r0 + 1 < M)
                *reinterpret_cast<__half2*>(C + (size_t)(r0 + 1) * N + tx * 2) =
                    __floats2half2_rn(u[0].y, u[1].y);
        }

        // fused es/ed from fp32 accumulators
        if (TN == 8) {
            float es0 = 0.f, ed0 = 0.f, es1 = 0.f, ed1 = 0.f;
            float es0h = 0.f, ed0h = 0.f, es1h = 0.f, ed1h = 0.f;
#pragma unroll
            for (int j = 0; j < 4; j++) {
                float aslo = s_as[tx * 4 + j], adlo = s_ad[tx * 4 + j];
                float ashi = s_as[64 + tx * 4 + j], adhi = s_ad[64 + tx * 4 + j];
                es0 += u[j].x * aslo;       ed0 += u[j].x * adlo;
                es1 += u[j].y * aslo;       ed1 += u[j].y * adlo;
                es0h += u[j + 4].x * ashi;  ed0h += u[j + 4].x * adhi;
                es1h += u[j + 4].y * ashi;  ed1h += u[j + 4].y * adhi;
            }
            if (H == 4) {
                es0 = red8(es0); ed0 = red8(ed0); es1 = red8(es1); ed1 = red8(ed1);
                es0h = red8(es0h); ed0h = red8(ed0h); es1h = red8(es1h); ed1h = red8(ed1h);
                if ((tx & 7) == 0) {
                    int hl = tx >> 3;
                    if (r0 < M) {
                        es[r0 * 4 + hl] = es0;      ed[r0 * 4 + hl] = ed0;
                        es[r0 * 4 + 2 + hl] = es0h; ed[r0 * 4 + 2 + hl] = ed0h;
                    }
                    if (r0 + 1 < M) {
                        es[(r0 + 1) * 4 + hl] = es1;      ed[(r0 + 1) * 4 + hl] = ed1;
                        es[(r0 + 1) * 4 + 2 + hl] = es1h; ed[(r0 + 1) * 4 + 2 + hl] = ed1h;
                    }
                }
            } else {
                es0 = red16(es0 + es0h); ed0 = red16(ed0 + ed0h);
                es1 = red16(es1 + es1h); ed1 = red16(ed1 + ed1h);
                if (tx == 0) {
                    if (r0 < M) { es[r0] = es0; ed[r0] = ed0; }
                    if (r0 + 1 < M) { es[r0 + 1] = es1; ed[r0 + 1] = ed1; }
                }
            }
        } else {
            float as0 = s_as[tx * 2], as1v = s_as[tx * 2 + 1];
            float ad0 = s_ad[tx * 2], ad1v = s_ad[tx * 2 + 1];
            float es0 = red16(u[0].x * as0 + u[1].x * as1v);
            float ed0 = red16(u[0].x * ad0 + u[1].x * ad1v);
            float es1 = red16(u[0].y * as0 + u[1].y * as1v);
            float ed1 = red16(u[0].y * ad0 + u[1].y * ad1v);
            if (tx == 0) {
                if (r0 < M) { es[r0] = es0; ed[r0] = ed0; }
                if (r0 + 1 < M) { es[r0 + 1] = es1; ed[r0 + 1] = ed1; }
            }
        }
    }
}

// ---------------- aggregation ----------------
__device__ __forceinline__ float lrelu(float a) { return a > 0.f ? a : 0.2f * a; }
__device__ __forceinline__ float ew(float z) { return __expf(fminf(z, 70.f)); }

template <int H>
__device__ __forceinline__ void load_esv(const float* __restrict__ es, int s, float* v) {
    if constexpr (H == 4) {
        float4 t = *reinterpret_cast<const float4*>(es + s * 4);
        v[0] = t.x; v[1] = t.y; v[2] = t.z; v[3] = t.w;
    } else {
        v[0] = es[s];
    }
}

// block-per-node variant for C = H*D = 128; block 0 also zeroes BN stats
template <int H, int D, bool RELU>
__global__ void agg_kernel(const __half* __restrict__ hbuf, const float* __restrict__ es,
                           const float* __restrict__ ed, const int* __restrict__ rowptr,
                           const int* __restrict__ csr, const float* __restrict__ bias,
                           float* __restrict__ out, float* __restrict__ stats) {
    constexpr int C = H * D;
    constexpr int NW = C / 32;
    const int node = blockIdx.x;
    const int tid = threadIdx.x;
    const int lane = tid & 31;
    const int wrp = tid >> 5;
    if (node == 0) { stats[tid] = 0.f; stats[tid + 128] = 0.f; }
    const int start = rowptr[node];
    const int deg = rowptr[node + 1] - start;

    __shared__ float s_ed[H];
    __shared__ float s_inv[H];
    __shared__ float s_red[NW * H];
    __shared__ float s_w[C * H];
    __shared__ int s_src[C];

    if (tid < H) s_ed[tid] = ed[node * H + tid];
    __syncthreads();
    float edv[H];
#pragma unroll
    for (int hh = 0; hh < H; hh++) edv[hh] = s_ed[hh];

    float sm[H];
#pragma unroll
    for (int hh = 0; hh < H; hh++) sm[hh] = 0.f;
    for (int e = tid; e < deg; e += C) {
        int s = csr[start + e];
        float evv[H], w[H];
        load_esv<H>(es, s, evv);
#pragma unroll
        for (int hh = 0; hh < H; hh++) w[hh] = ew(lrelu(evv[hh] + edv[hh]));
        if (e < C) {
            s_src[e] = s;
#pragma unroll
            for (int hh = 0; hh < H; hh++) s_w[e * H + hh] = w[hh];
        }
#pragma unroll
        for (int hh = 0; hh < H; hh++) sm[hh] += w[hh];
    }
#pragma unroll
    for (int hh = 0; hh < H; hh++) {
#pragma unroll
        for (int off = 16; off; off >>= 1) sm[hh] += __shfl_xor_sync(0xffffffffu, sm[hh], off);
    }
    if (lane == 0) {
#pragma unroll
        for (int hh = 0; hh < H; hh++) s_red[wrp * H + hh] = sm[hh];
    }
    __syncthreads();
    if (tid < H) {
        float tsum = 0.f;
#pragma unroll
        for (int w2 = 0; w2 < NW; w2++) tsum += s_red[w2 * H + tid];
        s_inv[tid] = 1.f / tsum;
    }
    __syncthreads();

    const int head = tid / D;
    const float inv = s_inv[head];

    float acc = 0.f;
    int cn0 = min(deg, C);
#pragma unroll 4
    for (int j = 0; j < cn0; j++) {
        acc += s_w[j * H + head] * __half2float(hbuf[(size_t)s_src[j] * C + tid]);
    }
    for (int base = C; base < deg; base += C) {
        int cn = min(C, deg - base);
        __syncthreads();
        if (tid < cn) {
            int s = csr[start + base + tid];
            s_src[tid] = s;
            float evv[H];
            load_esv<H>(es, s, evv);
#pragma unroll
            for (int hh = 0; hh < H; hh++) s_w[tid * H + hh] = ew(lrelu(evv[hh] + edv[hh]));
        }
        __syncthreads();
#pragma unroll 4
        for (int j = 0; j < cn; j++) {
            acc += s_w[j * H + head] * __half2float(hbuf[(size_t)s_src[j] * C + tid]);
        }
    }
    float r = acc * inv + bias[tid];
    if (RELU) r = fmaxf(r, 0.f);
    out[(size_t)node * C + tid] = r;
}

// warp-per-node variant for C = 32 (H=1, D=32); block 0 zeroes BN stats
template <int NPB, bool RELU>
__global__ void agg_warp_kernel(const __half* __restrict__ hbuf, const float* __restrict__ es,
                                const float* __restrict__ ed, const int* __restrict__ rowptr,
                                const int* __restrict__ csr, const float* __restrict__ bias,
                                float* __restrict__ out, float* __restrict__ stats) {
    const int lane = threadIdx.x & 31;
    const int wrp = threadIdx.x >> 5;
    if (blockIdx.x == 0) stats[threadIdx.x] = 0.f;
    const int node = blockIdx.x * NPB + wrp;
    if (node >= NNODES) return;
    const int start = rowptr[node];
    const int deg = rowptr[node + 1] - start;
    const float edv = ed[node];

    __shared__ float s_w[NPB][32];
    __shared__ int s_src[NPB][32];

    float sm = 0.f;
    for (int e = lane; e < deg; e += 32) {
        int s = csr[start + e];
        float w = ew(lrelu(es[s] + edv));
        if (e < 32) { s_src[wrp][e] = s; s_w[wrp][e] = w; }
        sm += w;
    }
#pragma unroll
    for (int off = 16; off; off >>= 1) sm += __shfl_xor_sync(0xffffffffu, sm, off);
    const float inv = 1.f / sm;
    __syncwarp();

    float acc = 0.f;
    int cn0 = min(deg, 32);
#pragma unroll 4
    for (int j = 0; j < cn0; j++) {
        acc += s_w[wrp][j] * __half2float(hbuf[(size_t)s_src[wrp][j] * 32 + lane]);
    }
    for (int base = 32; base < deg; base += 32) {
        int cn = min(32, deg - base);
        __syncwarp();
        if (lane < cn) {
            int s = csr[start + base + lane];
            s_src[wrp][lane] = s;
            s_w[wrp][lane] = ew(lrelu(es[s] + edv));
        }
        __syncwarp();
#pragma unroll 4
        for (int j = 0; j < cn; j++) {
            acc += s_w[wrp][j] * __half2float(hbuf[(size_t)s_src[wrp][j] * 32 + lane]);
        }
    }
    float r = acc * inv + bias[lane];
    if (RELU) r = fmaxf(r, 0.f);
    out[(size_t)node * 32 + lane] = r;
}

// ---------------- batchnorm stats (sum / sumsq per channel) ----------------
__global__ void bn_stats_kernel(const float* __restrict__ x, float* __restrict__ stats, int C) {
    __shared__ float shs[512], shq[512];
    int c = threadIdx.x, ry = threadIdx.y;
    int R = blockDim.y;
    int r0 = blockIdx.x * 256;
    int rend = min(r0 + 256, NNODES);
    float s = 0.f, q = 0.f;
    for (int r = r0 + ry; r < rend; r += R) {
        float v = x[(size_t)r * C + c];
        s += v;
        q += v * v;
    }
    int t = ry * C + c;
    shs[t] = s;
    shq[t] = q;
    __syncthreads();
    if (ry == 0) {
        for (int k = 1; k < R; k++) {
            s += shs[k * C + c];
            q += shq[k * C + c];
        }
        atomicAdd(&stats[c], s);
        atomicAdd(&stats[C + c], q);
    }
}

// ---------------- host launch ----------------
extern "C" void kernel_launch(void* const* d_in, const int* in_sizes, int n_in,
                              void* d_out, int out_size) {
    const float* x   = (const float*)d_in[0];
    const int*   ei  = (const int*)d_in[1];
    const float* W1  = (const float*)d_in[2];
    const float* as1 = (const float*)d_in[3];
    const float* ad1 = (const float*)d_in[4];
    const float* b1  = (const float*)d_in[5];
    const float* g1  = (const float*)d_in[6];
    const float* be1 = (const float*)d_in[7];
    const float* W2  = (const float*)d_in[8];
    const float* as2 = (const float*)d_in[9];
    const float* ad2 = (const float*)d_in[10];
    const float* b2  = (const float*)d_in[11];
    const float* g2  = (const float*)d_in[12];
    const float* be2 = (const float*)d_in[13];
    const float* W3  = (const float*)d_in[14];
    const float* as3 = (const float*)d_in[15];
    const float* ad3 = (const float*)d_in[16];
    const float* b3  = (const float*)d_in[17];
    const float* W4  = (const float*)d_in[18];
    const float* as4 = (const float*)d_in[19];
    const float* ad4 = (const float*)d_in[20];
    const float* b4  = (const float*)d_in[21];
    const float* g4  = (const float*)d_in[22];
    const float* be4 = (const float*)d_in[23];
    const float* W5  = (const float*)d_in[24];
    const float* as5 = (const float*)d_in[25];
    const float* ad5 = (const float*)d_in[26];
    const float* b5  = (const float*)d_in[27];
    float* out = (float*)d_out;

    float *bufA, *bufB, *es, *ed, *stats;
    __half* h;
    int *deg, *rowptr, *cursor, *csr;
    cudaGetSymbolAddress((void**)&h, g_h);
    cudaGetSymbolAddress((void**)&bufA, g_bufA);
    cudaGetSymbolAddress((void**)&bufB, g_bufB);
    cudaGetSymbolAddress((void**)&es, g_es);
    cudaGetSymbolAddress((void**)&ed, g_ed);
    cudaGetSymbolAddress((void**)&stats, g_stats);
    cudaGetSymbolAddress((void**)&deg, g_deg);
    cudaGetSymbolAddress((void**)&rowptr, g_rowptr);
    cudaGetSymbolAddress((void**)&cursor, g_cursor);
    cudaGetSymbolAddress((void**)&csr, g_csr);

    const int* e_src = ei;
    const int* e_dst = ei + NEDGES;

    const int MBLK = (NNODES + 127) / 128;           // 391
    const int CNTBLK = (NEDGES + 255) / 256;         // 3125
    dim3 gblk(16, 16);

    // ---- deg init (self loop = 1), then layer-1 GEMM fused with edge count ----
    deg_init_kernel<<<(NNODES + 255) / 256, 256>>>(deg);
    gemm_kernel<128, 4, false, false, true><<<MBLK + CNTBLK, gblk>>>(
        x, W1, h, NNODES, 128, 128, nullptr, nullptr, nullptr, as1, ad1, es, ed, e_dst, deg);
    scan_kernel<<<1, 1024>>>(deg, rowptr, cursor);
    scatter_kernel<<<(TOTEDGES + 255) / 256, 256>>>(e_src, e_dst, cursor, csr);

    // ---- layer 1 aggregation; bn stats ----
    agg_kernel<4, 32, true><<<NNODES, 128>>>(h, es, ed, rowptr, csr, b1, bufA, stats);
    bn_stats_kernel<<<(NNODES + 255) / 256, dim3(128, 4)>>>(bufA, stats, 128);

    // ---- layer 2: bn1 fused; GAT(128 -> 4x32) + fused es/ed, relu; bn stats ----
    gemm_kernel<128, 4, true, false, false><<<MBLK, gblk>>>(
        bufA, W2, h, NNODES, 128, 128, stats, g1, be1, as2, ad2, es, ed, nullptr, nullptr);
    agg_kernel<4, 32, true><<<NNODES, 128>>>(h, es, ed, rowptr, csr, b2, bufB, stats);
    bn_stats_kernel<<<(NNODES + 255) / 256, dim3(128, 4)>>>(bufB, stats, 128);

    // ---- layer 3: bn2 fused; GAT(128 -> 32) + fused es/ed, relu ----
    gemm_kernel<32, 1, true, false, false><<<MBLK, gblk>>>(
        bufB, W3, h, NNODES, 128, 32, stats, g2, be2, as3, ad3, es, ed, nullptr, nullptr);
    agg_warp_kernel<8, true><<<(NNODES + 7) / 8, 256>>>(h, es, ed, rowptr, csr, b3, bufA, stats);

    // ---- layer 4: GAT(32 -> 32) + fused es/ed, relu; bn stats ----
    gemm_kernel<32, 1, false, false, false><<<MBLK, gblk>>>(
        bufA, W4, h, NNODES, 32, 32, nullptr, nullptr, nullptr, as4, ad4, es, ed, nullptr, nullptr);
    agg_warp_kernel<8, true><<<(NNODES + 7) / 8, 256>>>(h, es, ed, rowptr, csr, b4, bufB, stats);
    bn_stats_kernel<<<(NNODES + 255) / 256, dim3(32, 16)>>>(bufB, stats, 32);

    // ---- layer 5: relu(bn4) fused; GAT(32 -> 128) + fused es/ed, output ----
    gemm_kernel<128, 1, true, true, false><<<MBLK, gblk>>>(
        bufB, W5, h, NNODES, 32, 128, stats, g4, be4, as5, ad5, es, ed, nullptr, nullptr);
    agg_kernel<1, 128, false><<<NNODES, 128>>>(h, es, ed, rowptr, csr, b5, out, stats);
}

// round 17
// speedup vs baseline: 1.3311x; 1.3311x over previous
#include <cuda_runtime.h>
#include <cuda_fp16.h>

#define NNODES 50000
#define NEDGES 800000
#define TOTEDGES (NEDGES + NNODES)

// ---------------- scratch (no allocations allowed) ----------------
__device__ __align__(16) __half g_h[NNODES * 128];   // fp16 gather source
__device__ float g_bufA[NNODES * 128];
__device__ float g_bufB[NNODES * 128];
__device__ float g_es[NNODES * 4];
__device__ float g_ed[NNODES * 4];
__device__ float g_stats[256];
__device__ int   g_deg[NNODES];
__device__ int   g_rowptr[NNODES + 1];
__device__ int   g_cursor[NNODES];
__device__ int   g_csr[TOTEDGES];

// ---------------- f32x2 helpers ----------------
__device__ __forceinline__ void fma2(unsigned long long& d, unsigned long long a,
                                     unsigned long long b) {
    asm("fma.rn.f32x2 %0, %1, %2, %0;" : "+l"(d) : "l"(a), "l"(b));
}
__device__ __forceinline__ unsigned long long bcast2(float x) {
    unsigned long long r;
    asm("mov.b64 %0, {%1, %1};" : "=l"(r) : "f"(x));
    return r;
}
__device__ __forceinline__ float2 unpack2(unsigned long long p) {
    float2 f;
    asm("mov.b64 {%0, %1}, %2;" : "=f"(f.x), "=f"(f.y) : "l"(p));
    return f;
}
__device__ __forceinline__ unsigned h2u(__half2 h) {
    return *reinterpret_cast<unsigned*>(&h);
}
__device__ __forceinline__ float red8(float v) {
    v += __shfl_xor_sync(0xffffffffu, v, 1);
    v += __shfl_xor_sync(0xffffffffu, v, 2);
    v += __shfl_xor_sync(0xffffffffu, v, 4);
    return v;
}
__device__ __forceinline__ float red16(float v) {
    v += __shfl_xor_sync(0xffffffffu, v, 1);
    v += __shfl_xor_sync(0xffffffffu, v, 2);
    v += __shfl_xor_sync(0xffffffffu, v, 4);
    v += __shfl_xor_sync(0xffffffffu, v, 8);
    return v;
}

// ---------------- CSR build (round-15 proven sequence) ----------------
__global__ void deg_init_kernel(int* deg) {
    int i = blockIdx.x * blockDim.x + threadIdx.x;
    if (i < NNODES) deg[i] = 1;  // self loop
}

__global__ void count_kernel(const int* __restrict__ dst, int* __restrict__ deg) {
    int i = blockIdx.x * blockDim.x + threadIdx.x;
    if (i < NEDGES) atomicAdd(&deg[dst[i]], 1);
}

__global__ void scan_kernel(const int* __restrict__ deg, int* __restrict__ rowptr,
                            int* __restrict__ cursor) {
    __shared__ int part[1024];
    const int CH = (NNODES + 1023) / 1024;
    int t = threadIdx.x;
    int base = t * CH;
    int s = 0;
    for (int i = 0; i < CH; i++) {
        int idx = base + i;
        if (idx < NNODES) s += deg[idx];
    }
    part[t] = s;
    __syncthreads();
    for (int off = 1; off < 1024; off <<= 1) {
        int v = (t >= off) ? part[t - off] : 0;
        __syncthreads();
        part[t] += v;
        __syncthreads();
    }
    int run = (t == 0) ? 0 : part[t - 1];
    for (int i = 0; i < CH; i++) {
        int idx = base + i;
        if (idx < NNODES) {
            rowptr[idx] = run;
            cursor[idx] = run;
            run += deg[idx];
        }
    }
    if (t == 1023) rowptr[NNODES] = part[1023];
}

__global__ void scatter_self_kernel(int* __restrict__ cursor, int* __restrict__ csr) {
    int i = blockIdx.x * blockDim.x + threadIdx.x;
    if (i < NNODES) {
        int pos = atomicAdd(&cursor[i], 1);
        csr[pos] = i;
    }
}

__global__ void scatter_edges_kernel(const int* __restrict__ src, const int* __restrict__ dst,
                                     int* __restrict__ cursor, int* __restrict__ csr) {
    int i = blockIdx.x * blockDim.x + threadIdx.x;
    if (i < NEDGES) {
        int d = dst[i];
        int pos = atomicAdd(&cursor[d], 1);
        csr[pos] = src[i];
    }
}

// ---------------- SGEMM (f32x2) + fused BN-affine input + fused es/ed epilogue ----------------
template <int BN, int H, bool AFFINE, bool INRELU>
__launch_bounds__(256, 2)
__global__ void gemm_kernel(const float* __restrict__ A, const float* __restrict__ B,
                            __half* __restrict__ C, int M, int K, int N,
                            const float* __restrict__ stats, const float* __restrict__ g,
                            const float* __restrict__ be,
                            const float* __restrict__ a_src, const float* __restrict__ a_dst,
                            float* __restrict__ es, float* __restrict__ ed) {
    constexpr int BM = 128;
    constexpr int BK = 32;
    constexpr int TN = BN / 16;
    constexpr int LDA = BM + 4;

    __shared__ alignas(16) float AsT[BK * LDA];
    __shared__ alignas(16) float Bs[BK * BN];
    __shared__ float s_sc[128];
    __shared__ float s_sh[128];
    __shared__ float s_as[BN];
    __shared__ float s_ad[BN];

    const int tx = threadIdx.x, ty = threadIdx.y;
    const int t = ty * 16 + tx;
    const int rowBase = blockIdx.x * BM;

    if (t < BN) {
        s_as[t] = a_src[t];
        s_ad[t] = a_dst[t];
    }

    if (AFFINE) {
        const float invn = 1.f / (float)NNODES;
        for (int c = t; c < K; c += 256) {
            float mean = stats[c] * invn;
            float var = stats[K + c] * invn - mean * mean;
            float scv = g[c] * rsqrtf(var + 1e-5f);
            s_sc[c] = scv;
            s_sh[c] = be[c] - mean * scv;
        }
    }
    __syncthreads();

    unsigned long long acc[4][TN];
#pragma unroll
    for (int p = 0; p < 4; p++)
#pragma unroll
        for (int j = 0; j < TN; j++) acc[p][j] = 0ull;

    for (int k0 = 0; k0 < K; k0 += BK) {
#pragma unroll
        for (int i = t; i < BM * BK / 4; i += 256) {
            int r = i / (BK / 4);
            int kc = (i % (BK / 4)) * 4;
            int rg = rowBase + r;
            float4 v = make_float4(0.f, 0.f, 0.f, 0.f);
            if (rg < M) v = *reinterpret_cast<const float4*>(A + (size_t)rg * K + k0 + kc);
            if (AFFINE) {
                int c = k0 + kc;
                v.x = v.x * s_sc[c] + s_sh[c];
                v.y = v.y * s_sc[c + 1] + s_sh[c + 1];
                v.z = v.z * s_sc[c + 2] + s_sh[c + 2];
                v.w = v.w * s_sc[c + 3] + s_sh[c + 3];
                if (INRELU) {
                    v.x = fmaxf(v.x, 0.f); v.y = fmaxf(v.y, 0.f);
                    v.z = fmaxf(v.z, 0.f); v.w = fmaxf(v.w, 0.f);
                }
            }
            AsT[(kc + 0) * LDA + r] = v.x;
            AsT[(kc + 1) * LDA + r] = v.y;
            AsT[(kc + 2) * LDA + r] = v.z;
            AsT[(kc + 3) * LDA + r] = v.w;
        }
#pragma unroll
        for (int i = t; i < BK * BN / 4; i += 256) {
            int kk = i / (BN / 4);
            int c = (i % (BN / 4)) * 4;
            *reinterpret_cast<float4*>(&Bs[kk * BN + c]) =
                *reinterpret_cast<const float4*>(B + (size_t)(k0 + kk) * N + c);
        }
        __syncthreads();

#pragma unroll
        for (int kk = 0; kk < BK; kk++) {
            const float* arow = &AsT[kk * LDA];
            ulonglong2 aLo = *reinterpret_cast<const ulonglong2*>(arow + ty * 4);
            ulonglong2 aHi = *reinterpret_cast<const ulonglong2*>(arow + 64 + ty * 4);
            unsigned long long bb[TN];
            if (TN == 8) {
                float4 b0 = *reinterpret_cast<const float4*>(&Bs[kk * BN + tx * 4]);
                float4 b1 = *reinterpret_cast<const float4*>(&Bs[kk * BN + 64 + tx * 4]);
                bb[0] = bcast2(b0.x); bb[1] = bcast2(b0.y);
                bb[2] = bcast2(b0.z); bb[3] = bcast2(b0.w);
                bb[4] = bcast2(b1.x); bb[5] = bcast2(b1.y);
                bb[6] = bcast2(b1.z); bb[7] = bcast2(b1.w);
            } else {
                float2 b0 = *reinterpret_cast<const float2*>(&Bs[kk * BN + tx * 2]);
                bb[0] = bcast2(b0.x); bb[1] = bcast2(b0.y);
            }
#pragma unroll
            for (int j = 0; j < TN; j++) {
                fma2(acc[0][j], aLo.x, bb[j]);
                fma2(acc[1][j], aLo.y, bb[j]);
                fma2(acc[2][j], aHi.x, bb[j]);
                fma2(acc[3][j], aHi.y, bb[j]);
            }
        }
        __syncthreads();
    }

#pragma unroll
    for (int p = 0; p < 4; p++) {
        int r0 = rowBase + ((p < 2) ? (ty * 4 + 2 * p) : (64 + ty * 4 + 2 * (p - 2)));
        float2 u[TN];
#pragma unroll
        for (int j = 0; j < TN; j++) u[j] = unpack2(acc[p][j]);

        // C stores (fp16)
        if (TN == 8) {
            if (r0 < M) {
                uint2 lo, hi;
                lo.x = h2u(__floats2half2_rn(u[0].x, u[1].x));
                lo.y = h2u(__floats2half2_rn(u[2].x, u[3].x));
                hi.x = h2u(__floats2half2_rn(u[4].x, u[5].x));
                hi.y = h2u(__floats2half2_rn(u[6].x, u[7].x));
                *reinterpret_cast<uint2*>(C + (size_t)r0 * N + tx * 4) = lo;
                *reinterpret_cast<uint2*>(C + (size_t)r0 * N + 64 + tx * 4) = hi;
            }
            if (r0 + 1 < M) {
                uint2 lo, hi;
                lo.x = h2u(__floats2half2_rn(u[0].y, u[1].y));
                lo.y = h2u(__floats2half2_rn(u[2].y, u[3].y));
                hi.x = h2u(__floats2half2_rn(u[4].y, u[5].y));
                hi.y = h2u(__floats2half2_rn(u[6].y, u[7].y));
                *reinterpret_cast<uint2*>(C + (size_t)(r0 + 1) * N + tx * 4) = lo;
                *reinterpret_cast<uint2*>(C + (size_t)(r0 + 1) * N + 64 + tx * 4) = hi;
            }
        } else {
            if (r0 < M)
                *reinterpret_cast<__half2*>(C + (size_t)r0 * N + tx * 2) =
                    __floats2half2_rn(u[0].x, u[1].x);
            if (r0 + 1 < M)
                *reinterpret_cast<__half2*>(C + (size_t)(r0 + 1) * N + tx * 2) =
                    __floats2half2_rn(u[0].y, u[1].y);
        }

        // fused es/ed from fp32 accumulators
        if (TN == 8) {
            float es0 = 0.f, ed0 = 0.f, es1 = 0.f, ed1 = 0.f;
            float es0h = 0.f, ed0h = 0.f, es1h = 0.f, ed1h = 0.f;
#pragma unroll
            for (int j = 0; j < 4; j++) {
                float aslo = s_as[tx * 4 + j], adlo = s_ad[tx * 4 + j];
                float ashi = s_as[64 + tx * 4 + j], adhi = s_ad[64 + tx * 4 + j];
                es0 += u[j].x * aslo;       ed0 += u[j].x * adlo;
                es1 += u[j].y * aslo;       ed1 += u[j].y * adlo;
                es0h += u[j + 4].x * ashi;  ed0h += u[j + 4].x * adhi;
                es1h += u[j + 4].y * ashi;  ed1h += u[j + 4].y * adhi;
            }
            if (H == 4) {
                es0 = red8(es0); ed0 = red8(ed0); es1 = red8(es1); ed1 = red8(ed1);
                es0h = red8(es0h); ed0h = red8(ed0h); es1h = red8(es1h); ed1h = red8(ed1h);
                if ((tx & 7) == 0) {
                    int hl = tx >> 3;
                    if (r0 < M) {
                        es[r0 * 4 + hl] = es0;      ed[r0 * 4 + hl] = ed0;
                        es[r0 * 4 + 2 + hl] = es0h; ed[r0 * 4 + 2 + hl] = ed0h;
                    }
                    if (r0 + 1 < M) {
                        es[(r0 + 1) * 4 + hl] = es1;      ed[(r0 + 1) * 4 + hl] = ed1;
                        es[(r0 + 1) * 4 + 2 + hl] = es1h; ed[(r0 + 1) * 4 + 2 + hl] = ed1h;
                    }
                }
            } else {
                es0 = red16(es0 + es0h); ed0 = red16(ed0 + ed0h);
                es1 = red16(es1 + es1h); ed1 = red16(ed1 + ed1h);
                if (tx == 0) {
                    if (r0 < M) { es[r0] = es0; ed[r0] = ed0; }
                    if (r0 + 1 < M) { es[r0 + 1] = es1; ed[r0 + 1] = ed1; }
                }
            }
        } else {
            float as0 = s_as[tx * 2], as1v = s_as[tx * 2 + 1];
            float ad0 = s_ad[tx * 2], ad1v = s_ad[tx * 2 + 1];
            float es0 = red16(u[0].x * as0 + u[1].x * as1v);
            float ed0 = red16(u[0].x * ad0 + u[1].x * ad1v);
            float es1 = red16(u[0].y * as0 + u[1].y * as1v);
            float ed1 = red16(u[0].y * ad0 + u[1].y * ad1v);
            if (tx == 0) {
                if (r0 < M) { es[r0] = es0; ed[r0] = ed0; }
                if (r0 + 1 < M) { es[r0 + 1] = es1; ed[r0 + 1] = ed1; }
            }
        }
    }
}

// ---------------- aggregation ----------------
__device__ __forceinline__ float lrelu(float a) { return a > 0.f ? a : 0.2f * a; }
__device__ __forceinline__ float ew(float z) { return __expf(fminf(z, 70.f)); }

// warp-per-node for C = 128 channels (H = 4 stride-4 es/ed, or H = 1 stride-1).
// 8 warps/block; lane owns 4 channels (one uint2 = 4 fp16 per edge).
// Weights for the first 128 edges cached per-warp in shared; rare tail recomputed.
template <int H, bool RELU>
__launch_bounds__(256)
__global__ void agg_wide_kernel(const __half* __restrict__ hbuf, const float* __restrict__ es,
                                const float* __restrict__ ed, const int* __restrict__ rowptr,
                                const int* __restrict__ csr, const float* __restrict__ bias,
                                float* __restrict__ out, float* __restrict__ stats) {
    const int lane = threadIdx.x & 31;
    const int wrp = threadIdx.x >> 5;   // 0..7
    if (blockIdx.x == 0) stats[threadIdx.x] = 0.f;
    const int node = blockIdx.x * 8 + wrp;
    if (node >= NNODES) return;
    const int start = rowptr[node];
    const int deg = rowptr[node + 1] - start;

    __shared__ float s_w[8][128 * H];
    __shared__ int s_src[8][128];

    float edq0, edq1, edq2, edq3;
    if (H == 4) {
        float4 t4 = *reinterpret_cast<const float4*>(ed + (size_t)node * 4);
        edq0 = t4.x; edq1 = t4.y; edq2 = t4.z; edq3 = t4.w;
    } else {
        edq0 = ed[node]; edq1 = edq2 = edq3 = 0.f;
    }

    // pass A: per-edge weights; cache first 128; accumulate denominators
    float sm0 = 0.f, sm1 = 0.f, sm2 = 0.f, sm3 = 0.f;
    for (int e = lane; e < deg; e += 32) {
        int s = csr[start + e];
        float w0, w1 = 0.f, w2 = 0.f, w3 = 0.f;
        if (H == 4) {
            float4 eq = *reinterpret_cast<const float4*>(es + (size_t)s * 4);
            w0 = ew(lrelu(eq.x + edq0)); w1 = ew(lrelu(eq.y + edq1));
            w2 = ew(lrelu(eq.z + edq2)); w3 = ew(lrelu(eq.w + edq3));
        } else {
            w0 = ew(lrelu(es[s] + edq0));
        }
        if (e < 128) {
            s_src[wrp][e] = s;
            if (H == 4)
                *reinterpret_cast<float4*>(&s_w[wrp][e * 4]) = make_float4(w0, w1, w2, w3);
            else
                s_w[wrp][e] = w0;
        }
        sm0 += w0; sm1 += w1; sm2 += w2; sm3 += w3;
    }
    sm0 = red16(sm0 + __shfl_xor_sync(0xffffffffu, sm0, 16));
    if (H == 4) {
        sm1 = red16(sm1 + __shfl_xor_sync(0xffffffffu, sm1, 16));
        sm2 = red16(sm2 + __shfl_xor_sync(0xffffffffu, sm2, 16));
        sm3 = red16(sm3 + __shfl_xor_sync(0xffffffffu, sm3, 16));
    }
    const int head = (H == 4) ? (lane >> 3) : 0;
    float denom = sm0;
    if (H == 4) denom = (head == 0) ? sm0 : (head == 1) ? sm1 : (head == 2) ? sm2 : sm3;
    const float inv = 1.f / denom;
    const float edh = (H == 4) ? ((head == 0) ? edq0 : (head == 1) ? edq1
                                  : (head == 2) ? edq2 : edq3)
                               : edq0;
    __syncwarp();

    // pass B: weighted gather; lane owns channels 4*lane .. 4*lane+3
    float4 acc = make_float4(0.f, 0.f, 0.f, 0.f);
    const int cached = min(deg, 128);
    for (int j = 0; j < cached; j++) {
        float wj = s_w[wrp][j * H + head];
        uint2 hv = *reinterpret_cast<const uint2*>(
            hbuf + (size_t)s_src[wrp][j] * 128 + lane * 4);
        float2 f01 = __half22float2(*reinterpret_cast<__half2*>(&hv.x));
        float2 f23 = __half22float2(*reinterpret_cast<__half2*>(&hv.y));
        acc.x += wj * f01.x; acc.y += wj * f01.y;
        acc.z += wj * f23.x; acc.w += wj * f23.y;
    }
    for (int j = 128; j < deg; j++) {
        int s = csr[start + j];
        float wj;
        if (H == 4) {
            float4 eq = *reinterpret_cast<const float4*>(es + (size_t)s * 4);
            float ev = (head == 0) ? eq.x : (head == 1) ? eq.y : (head == 2) ? eq.z : eq.w;
            wj = ew(lrelu(ev + edh));
        } else {
            wj = ew(lrelu(es[s] + edh));
        }
        uint2 hv = *reinterpret_cast<const uint2*>(hbuf + (size_t)s * 128 + lane * 4);
        float2 f01 = __half22float2(*reinterpret_cast<__half2*>(&hv.x));
        float2 f23 = __half22float2(*reinterpret_cast<__half2*>(&hv.y));
        acc.x += wj * f01.x; acc.y += wj * f01.y;
        acc.z += wj * f23.x; acc.w += wj * f23.y;
    }

    float4 bi = *reinterpret_cast<const float4*>(bias + lane * 4);
    float4 r;
    r.x = acc.x * inv + bi.x;
    r.y = acc.y * inv + bi.y;
    r.z = acc.z * inv + bi.z;
    r.w = acc.w * inv + bi.w;
    if (RELU) {
        r.x = fmaxf(r.x, 0.f); r.y = fmaxf(r.y, 0.f);
        r.z = fmaxf(r.z, 0.f); r.w = fmaxf(r.w, 0.f);
    }
    *reinterpret_cast<float4*>(out + (size_t)node * 128 + lane * 4) = r;
}

// warp-per-node variant for C = 32 (H=1, D=32); block 0 zeroes BN stats
template <int NPB, bool RELU>
__global__ void agg_warp_kernel(const __half* __restrict__ hbuf, const float* __restrict__ es,
                                const float* __restrict__ ed, const int* __restrict__ rowptr,
                                const int* __restrict__ csr, const float* __restrict__ bias,
                                float* __restrict__ out, float* __restrict__ stats) {
    const int lane = threadIdx.x & 31;
    const int wrp = threadIdx.x >> 5;
    if (blockIdx.x == 0) stats[threadIdx.x] = 0.f;
    const int node = blockIdx.x * NPB + wrp;
    if (node >= NNODES) return;
    const int start = rowptr[node];
    const int deg = rowptr[node + 1] - start;
    const float edv = ed[node];

    __shared__ float s_w[NPB][32];
    __shared__ int s_src[NPB][32];

    float sm = 0.f;
    for (int e = lane; e < deg; e += 32) {
        int s = csr[start + e];
        float w = ew(lrelu(es[s] + edv));
        if (e < 32) { s_src[wrp][e] = s; s_w[wrp][e] = w; }
        sm += w;
    }
#pragma unroll
    for (int off = 16; off; off >>= 1) sm += __shfl_xor_sync(0xffffffffu, sm, off);
    const float inv = 1.f / sm;
    __syncwarp();

    float acc = 0.f;
    int cn0 = min(deg, 32);
#pragma unroll 4
    for (int j = 0; j < cn0; j++) {
        acc += s_w[wrp][j] * __half2float(hbuf[(size_t)s_src[wrp][j] * 32 + lane]);
    }
    for (int base = 32; base < deg; base += 32) {
        int cn = min(32, deg - base);
        __syncwarp();
        if (lane < cn) {
            int s = csr[start + base + lane];
            s_src[wrp][lane] = s;
            s_w[wrp][lane] = ew(lrelu(es[s] + edv));
        }
        __syncwarp();
#pragma unroll 4
        for (int j = 0; j < cn; j++) {
            acc += s_w[wrp][j] * __half2float(hbuf[(size_t)s_src[wrp][j] * 32 + lane]);
        }
    }
    float r = acc * inv + bias[lane];
    if (RELU) r = fmaxf(r, 0.f);
    out[(size_t)node * 32 + lane] = r;
}

// ---------------- batchnorm stats (sum / sumsq per channel) ----------------
__global__ void bn_stats_kernel(const float* __restrict__ x, float* __restrict__ stats, int C) {
    __shared__ float shs[512], shq[512];
    int c = threadIdx.x, ry = threadIdx.y;
    int R = blockDim.y;
    int r0 = blockIdx.x * 256;
    int rend = min(r0 + 256, NNODES);
    float s = 0.f, q = 0.f;
    for (int r = r0 + ry; r < rend; r += R) {
        float v = x[(size_t)r * C + c];
        s += v;
        q += v * v;
    }
    int t = ry * C + c;
    shs[t] = s;
    shq[t] = q;
    __syncthreads();
    if (ry == 0) {
        for (int k = 1; k < R; k++) {
            s += shs[k * C + c];
            q += shq[k * C + c];
        }
        atomicAdd(&stats[c], s);
        atomicAdd(&stats[C + c], q);
    }
}

// ---------------- host launch ----------------
extern "C" void kernel_launch(void* const* d_in, const int* in_sizes, int n_in,
                              void* d_out, int out_size) {
    const float* x   = (const float*)d_in[0];
    const int*   ei  = (const int*)d_in[1];
    const float* W1  = (const float*)d_in[2];
    const float* as1 = (const float*)d_in[3];
    const float* ad1 = (const float*)d_in[4];
    const float* b1  = (const float*)d_in[5];
    const float* g1  = (const float*)d_in[6];
    const float* be1 = (const float*)d_in[7];
    const float* W2  = (const float*)d_in[8];
    const float* as2 = (const float*)d_in[9];
    const float* ad2 = (const float*)d_in[10];
    const float* b2  = (const float*)d_in[11];
    const float* g2  = (const float*)d_in[12];
    const float* be2 = (const float*)d_in[13];
    const float* W3  = (const float*)d_in[14];
    const float* as3 = (const float*)d_in[15];
    const float* ad3 = (const float*)d_in[16];
    const float* b3  = (const float*)d_in[17];
    const float* W4  = (const float*)d_in[18];
    const float* as4 = (const float*)d_in[19];
    const float* ad4 = (const float*)d_in[20];
    const float* b4  = (const float*)d_in[21];
    const float* g4  = (const float*)d_in[22];
    const float* be4 = (const float*)d_in[23];
    const float* W5  = (const float*)d_in[24];
    const float* as5 = (const float*)d_in[25];
    const float* ad5 = (const float*)d_in[26];
    const float* b5  = (const float*)d_in[27];
    float* out = (float*)d_out;

    float *bufA, *bufB, *es, *ed, *stats;
    __half* h;
    int *deg, *rowptr, *cursor, *csr;
    cudaGetSymbolAddress((void**)&h, g_h);
    cudaGetSymbolAddress((void**)&bufA, g_bufA);
    cudaGetSymbolAddress((void**)&bufB, g_bufB);
    cudaGetSymbolAddress((void**)&es, g_es);
    cudaGetSymbolAddress((void**)&ed, g_ed);
    cudaGetSymbolAddress((void**)&stats, g_stats);
    cudaGetSymbolAddress((void**)&deg, g_deg);
    cudaGetSymbolAddress((void**)&rowptr, g_rowptr);
    cudaGetSymbolAddress((void**)&cursor, g_cursor);
    cudaGetSymbolAddress((void**)&csr, g_csr);

    const int* e_src = ei;
    const int* e_dst = ei + NEDGES;

    // ---- build dst-CSR (with self loops; shared across all 5 layers) ----
    deg_init_kernel<<<(NNODES + 255) / 256, 256>>>(deg);
    count_kernel<<<(NEDGES + 255) / 256, 256>>>(e_dst, deg);
    scan_kernel<<<1, 1024>>>(deg, rowptr, cursor);
    scatter_self_kernel<<<(NNODES + 255) / 256, 256>>>(cursor, csr);
    scatter_edges_kernel<<<(NEDGES + 255) / 256, 256>>>(e_src, e_dst, cursor, csr);

    const int MBLK = (NNODES + 127) / 128;
    const int WBLK = (NNODES + 7) / 8;
    dim3 gblk(16, 16);

    // ---- layer 1: GAT(128 -> 4x32) + fused es/ed, relu; bn stats ----
    gemm_kernel<128, 4, false, false><<<MBLK, gblk>>>(
        x, W1, h, NNODES, 128, 128, nullptr, nullptr, nullptr, as1, ad1, es, ed);
    agg_wide_kernel<4, true><<<WBLK, 256>>>(h, es, ed, rowptr, csr, b1, bufA, stats);
    bn_stats_kernel<<<(NNODES + 255) / 256, dim3(128, 4)>>>(bufA, stats, 128);

    // ---- layer 2: bn1 fused; GAT(128 -> 4x32) + fused es/ed, relu; bn stats ----
    gemm_kernel<128, 4, true, false><<<MBLK, gblk>>>(
        bufA, W2, h, NNODES, 128, 128, stats, g1, be1, as2, ad2, es, ed);
    agg_wide_kernel<4, true><<<WBLK, 256>>>(h, es, ed, rowptr, csr, b2, bufB, stats);
    bn_stats_kernel<<<(NNODES + 255) / 256, dim3(128, 4)>>>(bufB, stats, 128);

    // ---- layer 3: bn2 fused; GAT(128 -> 32) + fused es/ed, relu ----
    gemm_kernel<32, 1, true, false><<<MBLK, gblk>>>(
        bufB, W3, h, NNODES, 128, 32, stats, g2, be2, as3, ad3, es, ed);
    agg_warp_kernel<8, true><<<WBLK, 256>>>(h, es, ed, rowptr, csr, b3, bufA, stats);

    // ---- layer 4: GAT(32 -> 32) + fused es/ed, relu; bn stats ----
    gemm_kernel<32, 1, false, false><<<MBLK, gblk>>>(
        bufA, W4, h, NNODES, 32, 32, nullptr, nullptr, nullptr, as4, ad4, es, ed);
    agg_warp_kernel<8, true><<<WBLK, 256>>>(h, es, ed, rowptr, csr, b4, bufB, stats);
    bn_stats_kernel<<<(NNODES + 255) / 256, dim3(32, 16)>>>(bufB, stats, 32);

    // ---- layer 5: relu(bn4) fused; GAT(32 -> 128) + fused es/ed, output ----
    gemm_kernel<128, 1, true, true><<<MBLK, gblk>>>(
        bufB, W5, h, NNODES, 32, 128, stats, g4, be4, as5, ad5, es, ed);
    agg_wide_kernel<1, false><<<WBLK, 256>>>(h, es, ed, rowptr, csr, b5, out, stats);
}